// round 6
// baseline (speedup 1.0000x reference)
#include <cuda_runtime.h>
#include <cstdint>

#define BB 64
#define TT 1024
#define II 128
#define HH 256

// y1 scratch: [B, T, H] fp32 = 64 MB
__device__ float g_y1[BB * TT * HH];

// ---------------------------------------------------------------- helpers
__device__ __forceinline__ uint32_t smem_u32(const void* p) {
    uint32_t a;
    asm("{ .reg .u64 t; cvta.to.shared.u64 t, %1; cvt.u32.u64 %0, t; }"
        : "=r"(a) : "l"(p));
    return a;
}
__device__ __forceinline__ uint32_t mapa_(uint32_t addr, uint32_t rank) {
    uint32_t ra;
    asm volatile("mapa.shared::cluster.u32 %0, %1, %2;" : "=r"(ra) : "r"(addr), "r"(rank));
    return ra;
}
__device__ __forceinline__ void st_async_f32_(uint32_t dst, float v, uint32_t mbar) {
    asm volatile("st.async.shared::cluster.mbarrier::complete_tx::bytes.b32 [%0], %1, [%2];"
                 :: "r"(dst), "r"(__float_as_uint(v)), "r"(mbar) : "memory");
}
__device__ __forceinline__ void mbar_init_(uint32_t mbar, uint32_t cnt) {
    asm volatile("mbarrier.init.shared.b64 [%0], %1;" :: "r"(mbar), "r"(cnt) : "memory");
}
__device__ __forceinline__ void mbar_expect_tx_(uint32_t mbar, uint32_t bytes) {
    asm volatile("mbarrier.arrive.expect_tx.shared.b64 _, [%0], %1;"
                 :: "r"(mbar), "r"(bytes) : "memory");
}
__device__ __forceinline__ void mbar_wait_(uint32_t mbar, uint32_t parity) {
    asm volatile(
        "{\n\t"
        ".reg .pred P;\n"
        "WL_%=:\n\t"
        "mbarrier.try_wait.parity.acquire.cluster.shared::cta.b64 P, [%0], %1;\n\t"
        "@!P bra WL_%=;\n\t"
        "}" :: "r"(mbar), "r"(parity) : "memory");
}
__device__ __forceinline__ void cluster_sync_() {
    asm volatile("barrier.cluster.arrive.aligned;" ::: "memory");
    asm volatile("barrier.cluster.wait.aligned;" ::: "memory");
}
__device__ __forceinline__ float sigmoid_(float z) {
    return __fdividef(1.0f, 1.0f + __expf(-z));
}
__device__ __forceinline__ float tanh_(float z) {
    return __fdividef(2.0f, 1.0f + __expf(-2.0f * z)) - 1.0f;
}

#define FMA16(af, ac, w0, w1, v)                                  \
    af = fmaf((w0).x, (v).x, af); af = fmaf((w0).y, (v).y, af);   \
    af = fmaf((w0).z, (v).z, af); af = fmaf((w0).w, (v).w, af);   \
    ac = fmaf((w1).x, (v).x, ac); ac = fmaf((w1).y, (v).y, ac);   \
    ac = fmaf((w1).z, (v).z, ac); ac = fmaf((w1).w, (v).w, ac);

#define BFLY(v, m)  v += __shfl_xor_sync(0xffffffffu, v, m)

// ================================================================ PASS 1
// Layer 1: cluster of 4 CTAs, 2 batch rows per cluster.
// CTA owns 64 j (BOTH gates), K=384 (x:128|h:256). 256 thr.
// Lane layout: lane = j_sub*4 + ks  (ks = lane&3, 4-way K-split IN-WARP),
// j = wid*8 + j_sub. After dot, 2 bfly stages reduce the K-split; every lane
// then holds ALL finals -> no SMEM partials, no reduce barrier.
// Phase-D roles by ks: row = ks&1, CTA-pair = ks>>1 (2 st.async each).

#define P1_TX 2048u   // 4 src CTAs x 2 rows x 64 j x 4B

struct P1Smem {
    float4 w4h[2][32][64];     // weights k4 in [64,96) : 65536 B
    float  comb[2][2][384];    // double-buffered [x_t | h] per row : 6144 B
    unsigned long long mbar[2];
};

__global__ void __cluster_dims__(4, 1, 1) __launch_bounds__(256, 1)
mgu_pass1(const float* __restrict__ x,
          const float* __restrict__ Wf1, const float* __restrict__ bf1,
          const float* __restrict__ Wc1, const float* __restrict__ bc1,
          float* __restrict__ out)
{
    extern __shared__ char raw[];
    P1Smem* s = reinterpret_cast<P1Smem*>(raw);

    const int tid  = threadIdx.x;
    const int lane = tid & 31;
    const int wid  = tid >> 5;
    const int rank = blockIdx.x & 3;
    const int cid  = blockIdx.x >> 2;
    const int b0   = cid * 2;

    const int ks    = lane & 3;        // in-warp K-split
    const int j_sub = lane >> 2;       // 0..7
    const int j     = wid * 8 + j_sub; // 0..63
    const int j0    = rank * 64;
    const int jg    = j0 + j;

    const int drow  = ks & 1;          // phase-D row for this lane
    const int dpair = ks >> 1;         // phase-D CTA pair

    const uint32_t mb0 = smem_u32(&s->mbar[0]);
    const uint32_t mb1 = smem_u32(&s->mbar[1]);

    // ---- register weights: q = 0..15 (k = 0..255)
    float4 wf[16], wc[16];
    #pragma unroll
    for (int q = 0; q < 16; ++q) {
        const int kb = (q * 4 + ks) * 4;
        wf[q] = make_float4(Wf1[(kb + 0) * HH + jg], Wf1[(kb + 1) * HH + jg],
                            Wf1[(kb + 2) * HH + jg], Wf1[(kb + 3) * HH + jg]);
        wc[q] = make_float4(Wc1[(kb + 0) * HH + jg], Wc1[(kb + 1) * HH + jg],
                            Wc1[(kb + 2) * HH + jg], Wc1[(kb + 3) * HH + jg]);
    }
    const float bfr = bf1[jg];
    const float bcr = bc1[jg];

    // ---- SMEM weights: k = 256..383 only
    for (int idx = tid; idx < 128 * 64; idx += 256) {
        int kk = idx >> 6, jj = idx & 63;
        int k = 256 + kk;
        reinterpret_cast<float*>(&s->w4h[0][kk >> 2][jj])[kk & 3] = Wf1[k * HH + j0 + jj];
        reinterpret_cast<float*>(&s->w4h[1][kk >> 2][jj])[kk & 3] = Wc1[k * HH + j0 + jj];
    }
    if (tid == 0) {
        mbar_init_(mb0, 1);  mbar_init_(mb1, 1);
        mbar_expect_tx_(mb0, P1_TX);  mbar_expect_tx_(mb1, P1_TX);
    }

    // ---- comb init: zero both buffers, then x(0)
    for (int idx = tid; idx < 2 * 2 * 384; idx += 256)
        reinterpret_cast<float*>(s->comb)[idx] = 0.0f;
    __syncthreads();
    if (tid < 64) {
        int row = tid >> 5, ch = tid & 31;
        reinterpret_cast<float4*>(&s->comb[0][row][0])[ch] =
            reinterpret_cast<const float4*>(&x[(b0 + row) * (TT * II)])[ch];
    }
    __syncthreads();
    cluster_sync_();   // peers' mbarriers + buffers ready before any st.async

    const int prow = tid >> 5, pch = tid & 31;   // x staging map (tid < 64)
    int ph0 = 0, ph1 = 0;

    for (int t = 0; t < TT; ++t) {
        const int cur = t & 1, nxt = cur ^ 1;

        float4 xv = make_float4(0.f, 0.f, 0.f, 0.f);
        if (tid < 64 && t + 1 < TT)
            xv = *reinterpret_cast<const float4*>(
                &x[(b0 + prow) * (TT * II) + (t + 1) * II + pch * 4]);

        const float4* cb0 = reinterpret_cast<const float4*>(s->comb[cur][0]);
        const float4* cb1 = reinterpret_cast<const float4*>(s->comb[cur][1]);
        float af0 = 0.f, ac0 = 0.f, af1 = 0.f, ac1 = 0.f;

        // ---- A: x-portion, register weights (hides mbar wait)
        #pragma unroll
        for (int q = 0; q < 8; ++q) {
            const int k4 = q * 4 + ks;
            float4 v0 = cb0[k4];
            float4 v1 = cb1[k4];
            FMA16(af0, ac0, wf[q], wc[q], v0)
            FMA16(af1, ac1, wf[q], wc[q], v1)
        }

        if (t) {
            if (t & 1) { mbar_wait_(mb1, ph1); ph1 ^= 1; }
            else       { mbar_wait_(mb0, ph0); ph0 ^= 1; }
            if (tid == 0) mbar_expect_tx_((t & 1) ? mb1 : mb0, P1_TX);  // re-arm t+2
        }

        // ---- B1: h-portion, register weights
        #pragma unroll
        for (int q = 8; q < 16; ++q) {
            const int k4 = q * 4 + ks;
            float4 v0 = cb0[k4];
            float4 v1 = cb1[k4];
            FMA16(af0, ac0, wf[q], wc[q], v0)
            FMA16(af1, ac1, wf[q], wc[q], v1)
        }
        // ---- B2: h-portion tail, SMEM weights (k4 64..95)
        #pragma unroll
        for (int q = 0; q < 8; ++q) {
            const int k4 = 64 + q * 4 + ks;
            float4 w0 = s->w4h[0][k4 - 64][j];
            float4 w1 = s->w4h[1][k4 - 64][j];
            float4 v0 = cb0[k4];
            float4 v1 = cb1[k4];
            FMA16(af0, ac0, w0, w1, v0)
            FMA16(af1, ac1, w0, w1, v1)
        }

        // stage x(t+1)
        if (tid < 64 && t + 1 < TT)
            reinterpret_cast<float4*>(&s->comb[nxt][prow][0])[pch] = xv;

        // ---- butterfly reduce over ks (lane bits 0..1): all lanes get finals
        BFLY(af0, 1); BFLY(ac0, 1); BFLY(af1, 1); BFLY(ac1, 1);
        BFLY(af0, 2); BFLY(ac0, 2); BFLY(af1, 2); BFLY(ac1, 2);

        // ---- D: activation + h update + st.async (role = (drow, dpair))
        {
            float pf = (drow ? af1 : af0) + bfr;
            float pc = (drow ? ac1 : ac0) + bcr;
            float f = sigmoid_(pf);
            float c = tanh_(pc);
            float hold = s->comb[cur][drow][II + jg];
            float hn   = fmaf(f, hold - c, c);     // f*h + (1-f)*c

            if (t + 1 < TT) {
                uint32_t la = smem_u32(&s->comb[nxt][drow][II + jg]);
                uint32_t lm = ((t + 1) & 1) ? mb1 : mb0;
                st_async_f32_(mapa_(la, (uint32_t)(dpair * 2)), hn,
                              mapa_(lm, (uint32_t)(dpair * 2)));
                st_async_f32_(mapa_(la, (uint32_t)(dpair * 2 + 1)), hn,
                              mapa_(lm, (uint32_t)(dpair * 2 + 1)));
            }
            if (ks < 2) {   // one writer per (row, j)
                g_y1[(b0 + drow) * (TT * HH) + t * HH + jg] = hn;
                if (t == TT - 1)
                    out[BB * TT * HH + (b0 + drow) * HH + jg] = hn;  // hidden L0
            }
        }
        __syncthreads();   // protects x staging for next step's dot-A
    }
    cluster_sync_();   // exit insurance
}

// ================================================================ PASS 2
// Layer 2: cluster of 8 CTAs, 4 batch rows per cluster.
// CTA owns 32 j (BOTH gates), K=512 (y1:256|h:256). 256 thr.
// Lane layout: lane = j_sub*8 + ks (8-way in-warp K-split), j = wid*4 + j_sub.
// 3 bfly stages; phase-D roles: row = ks&3, CTA-half = ks>>2 (4 st.async each).
// ALL weights register-resident.

#define P2_TX 4096u   // 8 src CTAs x 4 rows x 32 j x 4B

struct P2Smem {
    float  comb[2][4][512];    // 16384 B
    unsigned long long mbar[2];
};

__global__ void __cluster_dims__(8, 1, 1) __launch_bounds__(256, 1)
mgu_pass2(const float* __restrict__ Wf2, const float* __restrict__ bf2,
          const float* __restrict__ Wc2, const float* __restrict__ bc2,
          float* __restrict__ out)
{
    extern __shared__ char raw[];
    P2Smem* s = reinterpret_cast<P2Smem*>(raw);

    const int tid  = threadIdx.x;
    const int lane = tid & 31;
    const int wid  = tid >> 5;
    const int rank = blockIdx.x & 7;
    const int cid  = blockIdx.x >> 3;
    const int b0   = cid * 4;

    const int ks    = lane & 7;        // in-warp K-split
    const int j_sub = lane >> 3;       // 0..3
    const int j     = wid * 4 + j_sub; // 0..31
    const int j0    = rank * 32;
    const int jg    = j0 + j;

    const int drow  = ks & 3;          // phase-D row
    const int dhalf = ks >> 2;         // phase-D CTA half

    const uint32_t mb0 = smem_u32(&s->mbar[0]);
    const uint32_t mb1 = smem_u32(&s->mbar[1]);

    // ---- ALL weights into registers: q = 0..15, k4 = q*8+ks
    float4 wf[16], wc[16];
    #pragma unroll
    for (int q = 0; q < 16; ++q) {
        const int kb = (q * 8 + ks) * 4;
        wf[q] = make_float4(Wf2[(kb + 0) * HH + jg], Wf2[(kb + 1) * HH + jg],
                            Wf2[(kb + 2) * HH + jg], Wf2[(kb + 3) * HH + jg]);
        wc[q] = make_float4(Wc2[(kb + 0) * HH + jg], Wc2[(kb + 1) * HH + jg],
                            Wc2[(kb + 2) * HH + jg], Wc2[(kb + 3) * HH + jg]);
    }
    const float bfr = bf2[jg];
    const float bcr = bc2[jg];

    if (tid == 0) {
        mbar_init_(mb0, 1);  mbar_init_(mb1, 1);
        mbar_expect_tx_(mb0, P2_TX);  mbar_expect_tx_(mb1, P2_TX);
    }

    for (int idx = tid; idx < 2 * 4 * 512; idx += 256)
        reinterpret_cast<float*>(s->comb)[idx] = 0.0f;
    __syncthreads();
    {
        int row = tid >> 6, ch = tid & 63;    // 4 rows x 64 float4
        reinterpret_cast<float4*>(&s->comb[0][row][0])[ch] =
            reinterpret_cast<const float4*>(&g_y1[(b0 + row) * (TT * HH)])[ch];
    }
    __syncthreads();
    cluster_sync_();

    const int prow = tid >> 6, pch = tid & 63;
    int ph0 = 0, ph1 = 0;

    for (int t = 0; t < TT; ++t) {
        const int cur = t & 1, nxt = cur ^ 1;

        float4 yv = make_float4(0.f, 0.f, 0.f, 0.f);
        if (t + 1 < TT)
            yv = *reinterpret_cast<const float4*>(
                &g_y1[(b0 + prow) * (TT * HH) + (t + 1) * HH + pch * 4]);

        const float4* cb0 = reinterpret_cast<const float4*>(s->comb[cur][0]);
        const float4* cb1 = reinterpret_cast<const float4*>(s->comb[cur][1]);
        const float4* cb2 = reinterpret_cast<const float4*>(s->comb[cur][2]);
        const float4* cb3 = reinterpret_cast<const float4*>(s->comb[cur][3]);
        float af0 = 0.f, af1 = 0.f, af2 = 0.f, af3 = 0.f;
        float ac0 = 0.f, ac1 = 0.f, ac2 = 0.f, ac3 = 0.f;

        #pragma unroll
        for (int q = 0; q < 8; ++q) {          // A: y1 region
            const int k4 = q * 8 + ks;
            float4 v;
            v = cb0[k4]; FMA16(af0, ac0, wf[q], wc[q], v)
            v = cb1[k4]; FMA16(af1, ac1, wf[q], wc[q], v)
            v = cb2[k4]; FMA16(af2, ac2, wf[q], wc[q], v)
            v = cb3[k4]; FMA16(af3, ac3, wf[q], wc[q], v)
        }

        if (t) {
            if (t & 1) { mbar_wait_(mb1, ph1); ph1 ^= 1; }
            else       { mbar_wait_(mb0, ph0); ph0 ^= 1; }
            if (tid == 0) mbar_expect_tx_((t & 1) ? mb1 : mb0, P2_TX);
        }

        #pragma unroll
        for (int q = 8; q < 16; ++q) {         // B: h region
            const int k4 = q * 8 + ks;
            float4 v;
            v = cb0[k4]; FMA16(af0, ac0, wf[q], wc[q], v)
            v = cb1[k4]; FMA16(af1, ac1, wf[q], wc[q], v)
            v = cb2[k4]; FMA16(af2, ac2, wf[q], wc[q], v)
            v = cb3[k4]; FMA16(af3, ac3, wf[q], wc[q], v)
        }

        if (t + 1 < TT)
            reinterpret_cast<float4*>(&s->comb[nxt][prow][0])[pch] = yv;

        // ---- butterfly reduce over ks (lane bits 0..2)
        BFLY(af0, 1); BFLY(af1, 1); BFLY(af2, 1); BFLY(af3, 1);
        BFLY(ac0, 1); BFLY(ac1, 1); BFLY(ac2, 1); BFLY(ac3, 1);
        BFLY(af0, 2); BFLY(af1, 2); BFLY(af2, 2); BFLY(af3, 2);
        BFLY(ac0, 2); BFLY(ac1, 2); BFLY(ac2, 2); BFLY(ac3, 2);
        BFLY(af0, 4); BFLY(af1, 4); BFLY(af2, 4); BFLY(af3, 4);
        BFLY(ac0, 4); BFLY(ac1, 4); BFLY(ac2, 4); BFLY(ac3, 4);

        // ---- D: activation + h update + st.async (role = (drow, dhalf))
        {
            float pf = (drow == 0) ? af0 : (drow == 1) ? af1 : (drow == 2) ? af2 : af3;
            float pc = (drow == 0) ? ac0 : (drow == 1) ? ac1 : (drow == 2) ? ac2 : ac3;
            pf += bfr;  pc += bcr;
            float f = sigmoid_(pf);
            float c = tanh_(pc);
            float hold = s->comb[cur][drow][HH + jg];
            float hn   = fmaf(f, hold - c, c);

            if (t + 1 < TT) {
                uint32_t la = smem_u32(&s->comb[nxt][drow][HH + jg]);
                uint32_t lm = ((t + 1) & 1) ? mb1 : mb0;
                #pragma unroll
                for (int p = 0; p < 4; ++p)
                    st_async_f32_(mapa_(la, (uint32_t)(dhalf * 4 + p)), hn,
                                  mapa_(lm, (uint32_t)(dhalf * 4 + p)));
            }
            if (ks < 4) {   // one writer per (row, j)
                out[(b0 + drow) * (TT * HH) + t * HH + jg] = hn;         // y2
                if (t == TT - 1)
                    out[BB * TT * HH + BB * HH + (b0 + drow) * HH + jg] = hn; // hidden L1
            }
        }
        __syncthreads();   // protects y staging for next step's dot-A
    }
    cluster_sync_();   // exit insurance
}

// ================================================================ launch
extern "C" void kernel_launch(void* const* d_in, const int* in_sizes, int n_in,
                              void* d_out, int out_size)
{
    (void)in_sizes; (void)n_in; (void)out_size;
    const float* x   = (const float*)d_in[0];
    const float* Wf1 = (const float*)d_in[1];
    const float* bf1 = (const float*)d_in[2];
    const float* Wc1 = (const float*)d_in[3];
    const float* bc1 = (const float*)d_in[4];
    const float* Wf2 = (const float*)d_in[5];
    const float* bf2 = (const float*)d_in[6];
    const float* Wc2 = (const float*)d_in[7];
    const float* bc2 = (const float*)d_in[8];
    float* out = (float*)d_out;

    cudaFuncSetAttribute(mgu_pass1, cudaFuncAttributeMaxDynamicSharedMemorySize,
                         (int)sizeof(P1Smem));
    cudaFuncSetAttribute(mgu_pass2, cudaFuncAttributeMaxDynamicSharedMemorySize,
                         (int)sizeof(P2Smem));

    mgu_pass1<<<128, 256, sizeof(P1Smem)>>>(x, Wf1, bf1, Wc1, bc1, out);
    mgu_pass2<<<128, 256, sizeof(P2Smem)>>>(Wf2, bf2, Wc2, bc2, out);
}

// round 8
// speedup vs baseline: 1.2795x; 1.2795x over previous
#include <cuda_runtime.h>
#include <cstdint>

#define BB 64
#define TT 1024
#define II 128
#define HH 256

typedef unsigned long long u64t;

// y1 scratch: [B, T, H] fp32 = 64 MB
__device__ float g_y1[BB * TT * HH];

// ---------------------------------------------------------------- helpers
__device__ __forceinline__ uint32_t smem_u32(const void* p) {
    uint32_t a;
    asm("{ .reg .u64 t; cvta.to.shared.u64 t, %1; cvt.u32.u64 %0, t; }"
        : "=r"(a) : "l"(p));
    return a;
}
__device__ __forceinline__ uint32_t mapa_(uint32_t addr, uint32_t rank) {
    uint32_t ra;
    asm volatile("mapa.shared::cluster.u32 %0, %1, %2;" : "=r"(ra) : "r"(addr), "r"(rank));
    return ra;
}
__device__ __forceinline__ void st_async_b64_(uint32_t dst, u64t v, uint32_t mbar) {
    asm volatile("st.async.shared::cluster.mbarrier::complete_tx::bytes.b64 [%0], %1, [%2];"
                 :: "r"(dst), "l"(v), "r"(mbar) : "memory");
}
__device__ __forceinline__ void mbar_init_(uint32_t mbar, uint32_t cnt) {
    asm volatile("mbarrier.init.shared.b64 [%0], %1;" :: "r"(mbar), "r"(cnt) : "memory");
}
__device__ __forceinline__ void mbar_expect_tx_(uint32_t mbar, uint32_t bytes) {
    asm volatile("mbarrier.arrive.expect_tx.shared.b64 _, [%0], %1;"
                 :: "r"(mbar), "r"(bytes) : "memory");
}
__device__ __forceinline__ void mbar_wait_(uint32_t mbar, uint32_t parity) {
    asm volatile(
        "{\n\t"
        ".reg .pred P;\n"
        "WL_%=:\n\t"
        "mbarrier.try_wait.parity.acquire.cluster.shared::cta.b64 P, [%0], %1;\n\t"
        "@!P bra WL_%=;\n\t"
        "}" :: "r"(mbar), "r"(parity) : "memory");
}
__device__ __forceinline__ void cluster_sync_() {
    asm volatile("barrier.cluster.arrive.aligned;" ::: "memory");
    asm volatile("barrier.cluster.wait.aligned;" ::: "memory");
}
__device__ __forceinline__ float sigmoid_(float z) {
    return __fdividef(1.0f, 1.0f + __expf(-z));
}
__device__ __forceinline__ float tanh_(float z) {
    return __fdividef(2.0f, 1.0f + __expf(-2.0f * z)) - 1.0f;
}

// ---- packed fp32x2 ops (sm_103a FFMA2 path)
__device__ __forceinline__ void fma2_(u64t& d, u64t a, u64t b) {
    asm("fma.rn.f32x2 %0, %1, %2, %0;" : "+l"(d) : "l"(a), "l"(b));
}
__device__ __forceinline__ u64t add2_(u64t a, u64t b) {
    u64t d; asm("add.rn.f32x2 %0, %1, %2;" : "=l"(d) : "l"(a), "l"(b)); return d;
}
__device__ __forceinline__ u64t pack2_(float lo, float hi) {
    u64t d; asm("mov.b64 %0, {%1, %2};" : "=l"(d) : "f"(lo), "f"(hi)); return d;
}
__device__ __forceinline__ void unpack2_(u64t v, float& lo, float& hi) {
    asm("mov.b64 {%0, %1}, %2;" : "=f"(lo), "=f"(hi) : "l"(v));
}

// Accumulator packing: (af, ac) per row in one u64.  Weight regs pre-packed
// (wf_k, wc_k).  comb stored DUPLICATED: pair k holds (v_k, v_k), so one
// LDS.128 feeds two FFMA2 with zero pack instructions.  FMA-pipe instruction
// count halves vs scalar FFMA.

// ================================================================ PASS 1
// Layer 1: cluster of 4 CTAs, 2 batch rows per cluster. (R5 structure)
// CTA owns 64 j (both gates packed), K=384 (x:128|h:256).
// 256 threads = j(64) x ks(4); k-slice k4 = q*4+ks (4 scalar k per q).
//   q 0..7  reg weights (x region, pre-wait) / q 8..15 reg (h) / q 16..23 SMEM (h).

#define P1_TX 4096u   // 4 src CTAs x 128 writers x 8B

struct P1Smem {
    u64t       w4hp[128][64];      // packed (wf,wc), scalar k 256..383 : 65536 B
    ulonglong2 comb[2][2][192];    // dup pairs [buf][row][k/2] : 12288 B
    ulonglong2 partial[256];       // (acc_row0, acc_row1) : 4096 B
    u64t       mbar[2];
};

__global__ void __cluster_dims__(4, 1, 1) __launch_bounds__(256, 1)
mgu_pass1(const float* __restrict__ x,
          const float* __restrict__ Wf1, const float* __restrict__ bf1,
          const float* __restrict__ Wc1, const float* __restrict__ bc1,
          float* __restrict__ out)
{
    extern __shared__ char raw[];
    P1Smem* s = reinterpret_cast<P1Smem*>(raw);

    const int tid  = threadIdx.x;
    const int rank = blockIdx.x & 3;
    const int cid  = blockIdx.x >> 2;
    const int b0   = cid * 2;
    const int j    = tid & 63;
    const int ks   = tid >> 6;        // 0..3
    const int j0   = rank * 64;
    const int jg_w = j0 + j;

    const uint32_t mb0 = smem_u32(&s->mbar[0]);
    const uint32_t mb1 = smem_u32(&s->mbar[1]);

    // ---- register weights packed (wf,wc): scalar k = (q*4+ks)*4 + i, q 0..15
    u64t wpk[64];
    #pragma unroll
    for (int q = 0; q < 16; ++q) {
        const int kb = (q * 4 + ks) * 4;
        #pragma unroll
        for (int i = 0; i < 4; ++i)
            wpk[q * 4 + i] = pack2_(Wf1[(kb + i) * HH + jg_w], Wc1[(kb + i) * HH + jg_w]);
    }
    const u64t bias2 = pack2_(bf1[j0 + (tid & 63)], bc1[j0 + (tid & 63)]);

    // ---- SMEM weights packed: scalar k 256..383
    for (int idx = tid; idx < 128 * 64; idx += 256) {
        int kk = idx >> 6, jj = idx & 63;
        s->w4hp[kk][jj] = pack2_(Wf1[(256 + kk) * HH + j0 + jj],
                                 Wc1[(256 + kk) * HH + j0 + jj]);
    }
    if (tid == 0) {
        mbar_init_(mb0, 1);  mbar_init_(mb1, 1);
        mbar_expect_tx_(mb0, P1_TX);  mbar_expect_tx_(mb1, P1_TX);
    }

    // ---- comb init: zero both buffers (dup layout), then x(0)
    for (int idx = tid; idx < 2 * 2 * 192 * 2; idx += 256)
        reinterpret_cast<u64t*>(s->comb)[idx] = 0ull;
    __syncthreads();
    if (tid < 64) {
        int row = tid >> 5, ch = tid & 31;
        float4 xv = *reinterpret_cast<const float4*>(&x[(b0 + row) * (TT * II) + ch * 4]);
        ulonglong2 d0, d1;
        d0.x = pack2_(xv.x, xv.x); d0.y = pack2_(xv.y, xv.y);
        d1.x = pack2_(xv.z, xv.z); d1.y = pack2_(xv.w, xv.w);
        s->comb[0][row][ch * 2]     = d0;
        s->comb[0][row][ch * 2 + 1] = d1;
    }
    __syncthreads();
    cluster_sync_();   // peers' mbarriers + buffers ready before any st.async

    const int prow = tid >> 5, pch = tid & 31;   // x staging map (tid < 64)
    int ph0 = 0, ph1 = 0;

    for (int t = 0; t < TT; ++t) {
        const int cur = t & 1, nxt = cur ^ 1;

        float4 xv = make_float4(0.f, 0.f, 0.f, 0.f);
        if (tid < 64 && t + 1 < TT)
            xv = *reinterpret_cast<const float4*>(
                &x[(b0 + prow) * (TT * II) + (t + 1) * II + pch * 4]);

        const ulonglong2* c0 = s->comb[cur][0];
        const ulonglong2* c1 = s->comb[cur][1];
        u64t a0 = 0ull, a1 = 0ull;     // packed (af,ac) for rows 0,1

        #define P1_STEP(q, base)                                            \
        {   ulonglong2 u0 = c0[(base) * 2], u1 = c0[(base) * 2 + 1];        \
            fma2_(a0, wpk[(q) * 4 + 0], u0.x);                              \
            fma2_(a0, wpk[(q) * 4 + 1], u0.y);                              \
            fma2_(a0, wpk[(q) * 4 + 2], u1.x);                              \
            fma2_(a0, wpk[(q) * 4 + 3], u1.y);                              \
            ulonglong2 v0 = c1[(base) * 2], v1 = c1[(base) * 2 + 1];        \
            fma2_(a1, wpk[(q) * 4 + 0], v0.x);                              \
            fma2_(a1, wpk[(q) * 4 + 1], v0.y);                              \
            fma2_(a1, wpk[(q) * 4 + 2], v1.x);                              \
            fma2_(a1, wpk[(q) * 4 + 3], v1.y);                              \
        }

        // ---- A: x region (hides mbar wait)
        #pragma unroll
        for (int q = 0; q < 8; ++q) P1_STEP(q, q * 4 + ks)

        if (t) {
            if (t & 1) { mbar_wait_(mb1, ph1); ph1 ^= 1; }
            else       { mbar_wait_(mb0, ph0); ph0 ^= 1; }
            if (tid == 0) mbar_expect_tx_((t & 1) ? mb1 : mb0, P1_TX);  // re-arm t+2
        }

        // ---- B1: h region, register weights
        #pragma unroll
        for (int q = 8; q < 16; ++q) P1_STEP(q, q * 4 + ks)

        // ---- B2: h tail, SMEM weights (k4 64..95)
        #pragma unroll
        for (int q = 0; q < 8; ++q) {
            const int k4 = 64 + q * 4 + ks;
            const int kk = (k4 - 64) * 4;
            u64t w0 = s->w4hp[kk + 0][j];
            u64t w1 = s->w4hp[kk + 1][j];
            u64t w2 = s->w4hp[kk + 2][j];
            u64t w3 = s->w4hp[kk + 3][j];
            ulonglong2 u0 = c0[k4 * 2], u1 = c0[k4 * 2 + 1];
            fma2_(a0, w0, u0.x); fma2_(a0, w1, u0.y);
            fma2_(a0, w2, u1.x); fma2_(a0, w3, u1.y);
            ulonglong2 v0 = c1[k4 * 2], v1 = c1[k4 * 2 + 1];
            fma2_(a1, w0, v0.x); fma2_(a1, w1, v0.y);
            fma2_(a1, w2, v1.x); fma2_(a1, w3, v1.y);
        }
        #undef P1_STEP

        // stage x(t+1) (dup layout)
        if (tid < 64 && t + 1 < TT) {
            ulonglong2 d0, d1;
            d0.x = pack2_(xv.x, xv.x); d0.y = pack2_(xv.y, xv.y);
            d1.x = pack2_(xv.z, xv.z); d1.y = pack2_(xv.w, xv.w);
            s->comb[nxt][prow][pch * 2]     = d0;
            s->comb[nxt][prow][pch * 2 + 1] = d1;
        }

        ulonglong2 pr; pr.x = a0; pr.y = a1;
        s->partial[tid] = pr;
        __syncthreads();

        // ---- D: 128 writers; other warps free-run into next step's dot-A
        if (tid < 128) {
            const int row = tid >> 6, jl = tid & 63;
            ulonglong2 q0 = s->partial[jl];
            ulonglong2 q1 = s->partial[64 + jl];
            ulonglong2 q2 = s->partial[128 + jl];
            ulonglong2 q3 = s->partial[192 + jl];
            u64t a = row ? add2_(add2_(q0.y, q1.y), add2_(q2.y, q3.y))
                         : add2_(add2_(q0.x, q1.x), add2_(q2.x, q3.x));
            a = add2_(a, bias2);
            float pf, pc; unpack2_(a, pf, pc);
            float f = sigmoid_(pf);
            float c = tanh_(pc);
            const int jg = j0 + jl;
            float hold = reinterpret_cast<const float*>(s->comb[cur][row])[(II + jg) * 2];
            float hn   = fmaf(f, hold - c, c);     // f*h + (1-f)*c

            if (t + 1 < TT) {
                uint32_t la = smem_u32(reinterpret_cast<const char*>(s->comb[nxt][row])
                                       + (size_t)(II + jg) * 8);
                uint32_t lm = ((t + 1) & 1) ? mb1 : mb0;
                u64t hp = pack2_(hn, hn);
                #pragma unroll
                for (int p = 0; p < 4; ++p)
                    st_async_b64_(mapa_(la, (uint32_t)p), hp, mapa_(lm, (uint32_t)p));
            }
            g_y1[(b0 + row) * (TT * HH) + t * HH + jg] = hn;
            if (t == TT - 1)
                out[BB * TT * HH + (b0 + row) * HH + jg] = hn;   // hidden layer 0
        }
    }
    cluster_sync_();   // exit insurance
}

// ================================================================ PASS 2
// Layer 2: cluster of 8 CTAs, 4 batch rows per cluster. (R5 structure)
// CTA owns 32 j (both gates packed), K=512 (y1:256|h:256).
// 256 threads = j(32) x ks(8); ALL weights register-resident (64 u64).

#define P2_TX 8192u   // 8 src CTAs x 128 writers x 8B

struct P2Smem {
    ulonglong2 comb[2][4][256];    // dup pairs : 32768 B
    ulonglong2 partial[256][2];    // [(a0,a1),(a2,a3)] : 8192 B
    u64t       mbar[2];
};

__global__ void __cluster_dims__(8, 1, 1) __launch_bounds__(256, 1)
mgu_pass2(const float* __restrict__ Wf2, const float* __restrict__ bf2,
          const float* __restrict__ Wc2, const float* __restrict__ bc2,
          float* __restrict__ out)
{
    extern __shared__ char raw[];
    P2Smem* s = reinterpret_cast<P2Smem*>(raw);

    const int tid  = threadIdx.x;
    const int rank = blockIdx.x & 7;
    const int cid  = blockIdx.x >> 3;
    const int b0   = cid * 4;
    const int j    = tid & 31;
    const int ks   = tid >> 5;        // 0..7 (one ks per warp)
    const int j0   = rank * 32;
    const int jg_w = j0 + j;

    const uint32_t mb0 = smem_u32(&s->mbar[0]);
    const uint32_t mb1 = smem_u32(&s->mbar[1]);

    // ---- ALL weights packed into registers: scalar k = (q*8+ks)*4 + i
    u64t wpk[64];
    #pragma unroll
    for (int q = 0; q < 16; ++q) {
        const int kb = (q * 8 + ks) * 4;
        #pragma unroll
        for (int i = 0; i < 4; ++i)
            wpk[q * 4 + i] = pack2_(Wf2[(kb + i) * HH + jg_w], Wc2[(kb + i) * HH + jg_w]);
    }
    const u64t bias2 = pack2_(bf2[j0 + (tid & 31)], bc2[j0 + (tid & 31)]);

    if (tid == 0) {
        mbar_init_(mb0, 1);  mbar_init_(mb1, 1);
        mbar_expect_tx_(mb0, P2_TX);  mbar_expect_tx_(mb1, P2_TX);
    }

    for (int idx = tid; idx < 2 * 4 * 256 * 2; idx += 256)
        reinterpret_cast<u64t*>(s->comb)[idx] = 0ull;
    __syncthreads();
    {
        int row = tid >> 6, ch = tid & 63;    // 4 rows x 64 float4
        float4 yv = *reinterpret_cast<const float4*>(&g_y1[(b0 + row) * (TT * HH) + ch * 4]);
        ulonglong2 d0, d1;
        d0.x = pack2_(yv.x, yv.x); d0.y = pack2_(yv.y, yv.y);
        d1.x = pack2_(yv.z, yv.z); d1.y = pack2_(yv.w, yv.w);
        s->comb[0][row][ch * 2]     = d0;
        s->comb[0][row][ch * 2 + 1] = d1;
    }
    __syncthreads();
    cluster_sync_();

    const int prow = tid >> 6, pch = tid & 63;
    int ph0 = 0, ph1 = 0;

    for (int t = 0; t < TT; ++t) {
        const int cur = t & 1, nxt = cur ^ 1;

        float4 yv = make_float4(0.f, 0.f, 0.f, 0.f);
        if (t + 1 < TT)
            yv = *reinterpret_cast<const float4*>(
                &g_y1[(b0 + prow) * (TT * HH) + (t + 1) * HH + pch * 4]);

        const ulonglong2* c0 = s->comb[cur][0];
        const ulonglong2* c1 = s->comb[cur][1];
        const ulonglong2* c2 = s->comb[cur][2];
        const ulonglong2* c3 = s->comb[cur][3];
        u64t a0 = 0ull, a1 = 0ull, a2 = 0ull, a3 = 0ull;

        #define P2_STEP(q)                                                   \
        {   const int base = ((q) * 8 + ks) * 2;                             \
            ulonglong2 u0 = c0[base], u1 = c0[base + 1];                     \
            fma2_(a0, wpk[(q)*4+0], u0.x); fma2_(a0, wpk[(q)*4+1], u0.y);    \
            fma2_(a0, wpk[(q)*4+2], u1.x); fma2_(a0, wpk[(q)*4+3], u1.y);    \
            u0 = c1[base]; u1 = c1[base + 1];                                \
            fma2_(a1, wpk[(q)*4+0], u0.x); fma2_(a1, wpk[(q)*4+1], u0.y);    \
            fma2_(a1, wpk[(q)*4+2], u1.x); fma2_(a1, wpk[(q)*4+3], u1.y);    \
            u0 = c2[base]; u1 = c2[base + 1];                                \
            fma2_(a2, wpk[(q)*4+0], u0.x); fma2_(a2, wpk[(q)*4+1], u0.y);    \
            fma2_(a2, wpk[(q)*4+2], u1.x); fma2_(a2, wpk[(q)*4+3], u1.y);    \
            u0 = c3[base]; u1 = c3[base + 1];                                \
            fma2_(a3, wpk[(q)*4+0], u0.x); fma2_(a3, wpk[(q)*4+1], u0.y);    \
            fma2_(a3, wpk[(q)*4+2], u1.x); fma2_(a3, wpk[(q)*4+3], u1.y);    \
        }

        #pragma unroll
        for (int q = 0; q < 8; ++q) P2_STEP(q)          // A: y1 region

        if (t) {
            if (t & 1) { mbar_wait_(mb1, ph1); ph1 ^= 1; }
            else       { mbar_wait_(mb0, ph0); ph0 ^= 1; }
            if (tid == 0) mbar_expect_tx_((t & 1) ? mb1 : mb0, P2_TX);
        }

        #pragma unroll
        for (int q = 8; q < 16; ++q) P2_STEP(q)         // B: h region
        #undef P2_STEP

        if (t + 1 < TT) {
            ulonglong2 d0, d1;
            d0.x = pack2_(yv.x, yv.x); d0.y = pack2_(yv.y, yv.y);
            d1.x = pack2_(yv.z, yv.z); d1.y = pack2_(yv.w, yv.w);
            s->comb[nxt][prow][pch * 2]     = d0;
            s->comb[nxt][prow][pch * 2 + 1] = d1;
        }

        ulonglong2 pa; pa.x = a0; pa.y = a1;
        ulonglong2 pb; pb.x = a2; pb.y = a3;
        s->partial[tid][0] = pa;
        s->partial[tid][1] = pb;
        __syncthreads();

        // ---- D: 128 writers; other warps free-run
        if (tid < 128) {
            const int row = tid >> 5, jl = tid & 31;
            const int half = row >> 1, odd = row & 1;
            u64t a;
            {
                ulonglong2 p0 = s->partial[jl][half];
                a = odd ? p0.y : p0.x;
                #pragma unroll
                for (int kk = 1; kk < 8; ++kk) {
                    ulonglong2 pk = s->partial[kk * 32 + jl][half];
                    a = add2_(a, odd ? pk.y : pk.x);
                }
            }
            a = add2_(a, bias2);
            float pf, pc; unpack2_(a, pf, pc);
            float f = sigmoid_(pf);
            float c = tanh_(pc);
            const int jg = j0 + jl;
            float hold = reinterpret_cast<const float*>(s->comb[cur][row])[(HH + jg) * 2];
            float hn   = fmaf(f, hold - c, c);

            if (t + 1 < TT) {
                uint32_t la = smem_u32(reinterpret_cast<const char*>(s->comb[nxt][row])
                                       + (size_t)(HH + jg) * 8);
                uint32_t lm = ((t + 1) & 1) ? mb1 : mb0;
                u64t hp = pack2_(hn, hn);
                #pragma unroll
                for (int p = 0; p < 8; ++p)
                    st_async_b64_(mapa_(la, (uint32_t)p), hp, mapa_(lm, (uint32_t)p));
            }
            out[(b0 + row) * (TT * HH) + t * HH + jg] = hn;              // y2
            if (t == TT - 1)
                out[BB * TT * HH + BB * HH + (b0 + row) * HH + jg] = hn; // hidden L1
        }
    }
    cluster_sync_();   // exit insurance
}

// ================================================================ launch
extern "C" void kernel_launch(void* const* d_in, const int* in_sizes, int n_in,
                              void* d_out, int out_size)
{
    (void)in_sizes; (void)n_in; (void)out_size;
    const float* x   = (const float*)d_in[0];
    const float* Wf1 = (const float*)d_in[1];
    const float* bf1 = (const float*)d_in[2];
    const float* Wc1 = (const float*)d_in[3];
    const float* bc1 = (const float*)d_in[4];
    const float* Wf2 = (const float*)d_in[5];
    const float* bf2 = (const float*)d_in[6];
    const float* Wc2 = (const float*)d_in[7];
    const float* bc2 = (const float*)d_in[8];
    float* out = (float*)d_out;

    cudaFuncSetAttribute(mgu_pass1, cudaFuncAttributeMaxDynamicSharedMemorySize,
                         (int)sizeof(P1Smem));
    cudaFuncSetAttribute(mgu_pass2, cudaFuncAttributeMaxDynamicSharedMemorySize,
                         (int)sizeof(P2Smem));

    mgu_pass1<<<128, 256, sizeof(P1Smem)>>>(x, Wf1, bf1, Wc1, bc1, out);
    mgu_pass2<<<128, 256, sizeof(P2Smem)>>>(Wf2, bf2, Wc2, bc2, out);
}

// round 9
// speedup vs baseline: 1.4049x; 1.0981x over previous
#include <cuda_runtime.h>
#include <cstdint>

#define BB 64
#define TT 1024
#define II 128
#define HH 256

// y1 scratch: [B, T, H] fp32 = 64 MB
__device__ float g_y1[BB * TT * HH];

// ---------------------------------------------------------------- helpers
__device__ __forceinline__ uint32_t smem_u32(const void* p) {
    uint32_t a;
    asm("{ .reg .u64 t; cvta.to.shared.u64 t, %1; cvt.u32.u64 %0, t; }"
        : "=r"(a) : "l"(p));
    return a;
}
__device__ __forceinline__ uint32_t mapa_(uint32_t addr, uint32_t rank) {
    uint32_t ra;
    asm volatile("mapa.shared::cluster.u32 %0, %1, %2;" : "=r"(ra) : "r"(addr), "r"(rank));
    return ra;
}
__device__ __forceinline__ void st_async_f32_(uint32_t dst, float v, uint32_t mbar) {
    asm volatile("st.async.shared::cluster.mbarrier::complete_tx::bytes.b32 [%0], %1, [%2];"
                 :: "r"(dst), "r"(__float_as_uint(v)), "r"(mbar) : "memory");
}
__device__ __forceinline__ void mbar_init_(uint32_t mbar, uint32_t cnt) {
    asm volatile("mbarrier.init.shared.b64 [%0], %1;" :: "r"(mbar), "r"(cnt) : "memory");
}
__device__ __forceinline__ void mbar_expect_tx_(uint32_t mbar, uint32_t bytes) {
    asm volatile("mbarrier.arrive.expect_tx.shared.b64 _, [%0], %1;"
                 :: "r"(mbar), "r"(bytes) : "memory");
}
__device__ __forceinline__ void mbar_wait_(uint32_t mbar, uint32_t parity) {
    asm volatile(
        "{\n\t"
        ".reg .pred P;\n"
        "WL_%=:\n\t"
        "mbarrier.try_wait.parity.acquire.cluster.shared::cta.b64 P, [%0], %1;\n\t"
        "@!P bra WL_%=;\n\t"
        "}" :: "r"(mbar), "r"(parity) : "memory");
}
__device__ __forceinline__ void cluster_sync_() {
    asm volatile("barrier.cluster.arrive.aligned;" ::: "memory");
    asm volatile("barrier.cluster.wait.aligned;" ::: "memory");
}
__device__ __forceinline__ float sigmoid_(float z) {
    return __fdividef(1.0f, 1.0f + __expf(-z));
}
__device__ __forceinline__ float tanh_(float z) {
    return __fdividef(2.0f, 1.0f + __expf(-2.0f * z)) - 1.0f;
}

#define FMA16(af, ac, w0, w1, v)                                  \
    af = fmaf((w0).x, (v).x, af); af = fmaf((w0).y, (v).y, af);   \
    af = fmaf((w0).z, (v).z, af); af = fmaf((w0).w, (v).w, af);   \
    ac = fmaf((w1).x, (v).x, ac); ac = fmaf((w1).y, (v).y, ac);   \
    ac = fmaf((w1).z, (v).z, ac); ac = fmaf((w1).w, (v).w, ac);

// ================================================================ PASS 1
// Layer 1: cluster of 4 CTAs, 2 batch rows per cluster.  (R5 structure)
// CTA owns 64 j (BOTH gates), K=384 (x:128|h:256). 256 thr = j(64) x ks(4).
//   q 0..7  : x region, REG weights, pre-wait
//   B2 first: h tail, SMEM weights (drains through LDS early)
//   B1 last : h region, REG weights (pure-register tail before partial store)
// Phase-D writers ALTERNATE per step: threads [0,128) on even t, [128,256) on
// odd t — pipelines the D-phase latency across warp halves.

#define P1_TX 2048u   // 4 src CTAs x 128 writers x 4B

struct P1Smem {
    float4 w4h[2][32][64];     // weights k4 in [64,96) : 65536 B
    float  comb[2][2][384];    // double-buffered [x_t | h] per row : 6144 B
    float4 partial[256];       // (af0, ac0, af1, ac1) : 4096 B
    float  biasf[64];
    float  biasc[64];          // 512 B
    unsigned long long mbar[2];
};

__global__ void __cluster_dims__(4, 1, 1) __launch_bounds__(256, 1)
mgu_pass1(const float* __restrict__ x,
          const float* __restrict__ Wf1, const float* __restrict__ bf1,
          const float* __restrict__ Wc1, const float* __restrict__ bc1,
          float* __restrict__ out)
{
    extern __shared__ char raw[];
    P1Smem* s = reinterpret_cast<P1Smem*>(raw);

    const int tid  = threadIdx.x;
    const int rank = blockIdx.x & 3;
    const int cid  = blockIdx.x >> 2;
    const int b0   = cid * 2;
    const int j    = tid & 63;
    const int ks   = tid >> 6;        // 0..3
    const int j0   = rank * 64;
    const int jg_w = j0 + j;

    const uint32_t mb0 = smem_u32(&s->mbar[0]);
    const uint32_t mb1 = smem_u32(&s->mbar[1]);

    // ---- register weights: q = 0..15 (k = 0..255)
    float4 wf[16], wc[16];
    #pragma unroll
    for (int q = 0; q < 16; ++q) {
        const int kb = (q * 4 + ks) * 4;
        wf[q] = make_float4(Wf1[(kb + 0) * HH + jg_w], Wf1[(kb + 1) * HH + jg_w],
                            Wf1[(kb + 2) * HH + jg_w], Wf1[(kb + 3) * HH + jg_w]);
        wc[q] = make_float4(Wc1[(kb + 0) * HH + jg_w], Wc1[(kb + 1) * HH + jg_w],
                            Wc1[(kb + 2) * HH + jg_w], Wc1[(kb + 3) * HH + jg_w]);
    }

    // ---- SMEM weights: k = 256..383 only
    for (int idx = tid; idx < 128 * 64; idx += 256) {
        int kk = idx >> 6, jj = idx & 63;
        int k = 256 + kk;
        reinterpret_cast<float*>(&s->w4h[0][kk >> 2][jj])[kk & 3] = Wf1[k * HH + j0 + jj];
        reinterpret_cast<float*>(&s->w4h[1][kk >> 2][jj])[kk & 3] = Wc1[k * HH + j0 + jj];
    }
    if (tid < 64) { s->biasf[tid] = bf1[j0 + tid]; s->biasc[tid] = bc1[j0 + tid]; }

    if (tid == 0) {
        mbar_init_(mb0, 1);  mbar_init_(mb1, 1);
        mbar_expect_tx_(mb0, P1_TX);  mbar_expect_tx_(mb1, P1_TX);
    }

    // ---- comb init: zero both buffers, then x(0)
    for (int idx = tid; idx < 2 * 2 * 384; idx += 256)
        reinterpret_cast<float*>(s->comb)[idx] = 0.0f;
    __syncthreads();
    if (tid < 64) {
        int row = tid >> 5, ch = tid & 31;
        reinterpret_cast<float4*>(&s->comb[0][row][0])[ch] =
            reinterpret_cast<const float4*>(&x[(b0 + row) * (TT * II)])[ch];
    }
    __syncthreads();
    cluster_sync_();   // peers' mbarriers + buffers ready before any st.async

    const int prow = tid >> 5, pch = tid & 31;   // x staging map (tid < 64)
    int ph0 = 0, ph1 = 0;

    for (int t = 0; t < TT; ++t) {
        const int cur = t & 1, nxt = cur ^ 1;

        float4 xv = make_float4(0.f, 0.f, 0.f, 0.f);
        if (tid < 64 && t + 1 < TT)
            xv = *reinterpret_cast<const float4*>(
                &x[(b0 + prow) * (TT * II) + (t + 1) * II + pch * 4]);

        const float4* cb0 = reinterpret_cast<const float4*>(s->comb[cur][0]);
        const float4* cb1 = reinterpret_cast<const float4*>(s->comb[cur][1]);
        float af0 = 0.f, ac0 = 0.f, af1 = 0.f, ac1 = 0.f;

        // ---- A: x-portion, register weights (hides mbar wait)
        #pragma unroll
        for (int q = 0; q < 8; ++q) {
            const int k4 = q * 4 + ks;
            float4 v0 = cb0[k4];
            float4 v1 = cb1[k4];
            FMA16(af0, ac0, wf[q], wc[q], v0)
            FMA16(af1, ac1, wf[q], wc[q], v1)
        }

        if (t) {
            if (t & 1) { mbar_wait_(mb1, ph1); ph1 ^= 1; }
            else       { mbar_wait_(mb0, ph0); ph0 ^= 1; }
            if (tid == 0) mbar_expect_tx_((t & 1) ? mb1 : mb0, P1_TX);  // re-arm t+2
        }

        // ---- B2 first: h tail, SMEM weights (k4 64..95) — LDS early
        #pragma unroll
        for (int q = 0; q < 8; ++q) {
            const int k4 = 64 + q * 4 + ks;
            float4 w0 = s->w4h[0][k4 - 64][j];
            float4 w1 = s->w4h[1][k4 - 64][j];
            float4 v0 = cb0[k4];
            float4 v1 = cb1[k4];
            FMA16(af0, ac0, w0, w1, v0)
            FMA16(af1, ac1, w0, w1, v1)
        }
        // ---- B1 last: h region, register weights — clean drain
        #pragma unroll
        for (int q = 8; q < 16; ++q) {
            const int k4 = q * 4 + ks;
            float4 v0 = cb0[k4];
            float4 v1 = cb1[k4];
            FMA16(af0, ac0, wf[q], wc[q], v0)
            FMA16(af1, ac1, wf[q], wc[q], v1)
        }

        // stage x(t+1)
        if (tid < 64 && t + 1 < TT)
            reinterpret_cast<float4*>(&s->comb[nxt][prow][0])[pch] = xv;

        s->partial[tid] = make_float4(af0, ac0, af1, ac1);
        __syncthreads();

        // ---- D: alternating writer half; other warps free-run
        const int wtid = tid - ((t & 1) << 7);
        if ((unsigned)wtid < 128u) {
            const int row = wtid >> 6, jl = wtid & 63;
            float4 p0 = s->partial[jl];
            float4 p1 = s->partial[64 + jl];
            float4 p2 = s->partial[128 + jl];
            float4 p3 = s->partial[192 + jl];
            float pf, pc;
            if (row == 0) { pf = (p0.x + p1.x) + (p2.x + p3.x);
                            pc = (p0.y + p1.y) + (p2.y + p3.y); }
            else          { pf = (p0.z + p1.z) + (p2.z + p3.z);
                            pc = (p0.w + p1.w) + (p2.w + p3.w); }
            pf += s->biasf[jl];
            pc += s->biasc[jl];
            float f = sigmoid_(pf);
            float c = tanh_(pc);
            const int jg = j0 + jl;
            float hold = s->comb[cur][row][II + jg];
            float hn   = fmaf(f, hold - c, c);     // f*h + (1-f)*c

            if (t + 1 < TT) {
                uint32_t la = smem_u32(&s->comb[nxt][row][II + jg]);
                uint32_t lm = ((t + 1) & 1) ? mb1 : mb0;
                #pragma unroll
                for (int p = 0; p < 4; ++p)
                    st_async_f32_(mapa_(la, (uint32_t)p), hn, mapa_(lm, (uint32_t)p));
            }
            g_y1[(b0 + row) * (TT * HH) + t * HH + jg] = hn;
            if (t == TT - 1)
                out[BB * TT * HH + (b0 + row) * HH + jg] = hn;   // hidden layer 0
        }
    }
    cluster_sync_();   // exit insurance
}

// ================================================================ PASS 2
// Layer 2: cluster of 8 CTAs, 4 batch rows per cluster.  (R5 structure)
// CTA owns 32 j (BOTH gates), K=512 (y1:256|h:256). 256 thr = j(32) x ks(8).
// ALL weights register-resident. Phase-D writers alternate per step.

#define P2_TX 4096u   // 8 src CTAs x 128 writers x 4B

struct P2Smem {
    float  comb[2][4][512];    // 16384 B
    float  partial[256][8];    // af[4] | ac[4] : 8192 B
    float  biasf[32];
    float  biasc[32];          // 256 B
    unsigned long long mbar[2];
};

__global__ void __cluster_dims__(8, 1, 1) __launch_bounds__(256, 1)
mgu_pass2(const float* __restrict__ Wf2, const float* __restrict__ bf2,
          const float* __restrict__ Wc2, const float* __restrict__ bc2,
          float* __restrict__ out)
{
    extern __shared__ char raw[];
    P2Smem* s = reinterpret_cast<P2Smem*>(raw);

    const int tid  = threadIdx.x;
    const int rank = blockIdx.x & 7;
    const int cid  = blockIdx.x >> 3;
    const int b0   = cid * 4;
    const int j    = tid & 31;
    const int ks   = tid >> 5;        // 0..7
    const int j0   = rank * 32;
    const int jg_w = j0 + j;

    const uint32_t mb0 = smem_u32(&s->mbar[0]);
    const uint32_t mb1 = smem_u32(&s->mbar[1]);

    // ---- ALL weights into registers: q = 0..15, k4 = q*8+ks
    float4 wf[16], wc[16];
    #pragma unroll
    for (int q = 0; q < 16; ++q) {
        const int kb = (q * 8 + ks) * 4;
        wf[q] = make_float4(Wf2[(kb + 0) * HH + jg_w], Wf2[(kb + 1) * HH + jg_w],
                            Wf2[(kb + 2) * HH + jg_w], Wf2[(kb + 3) * HH + jg_w]);
        wc[q] = make_float4(Wc2[(kb + 0) * HH + jg_w], Wc2[(kb + 1) * HH + jg_w],
                            Wc2[(kb + 2) * HH + jg_w], Wc2[(kb + 3) * HH + jg_w]);
    }
    if (tid < 32) { s->biasf[tid] = bf2[j0 + tid]; s->biasc[tid] = bc2[j0 + tid]; }

    if (tid == 0) {
        mbar_init_(mb0, 1);  mbar_init_(mb1, 1);
        mbar_expect_tx_(mb0, P2_TX);  mbar_expect_tx_(mb1, P2_TX);
    }

    for (int idx = tid; idx < 2 * 4 * 512; idx += 256)
        reinterpret_cast<float*>(s->comb)[idx] = 0.0f;
    __syncthreads();
    {
        int row = tid >> 6, ch = tid & 63;    // 4 rows x 64 float4
        reinterpret_cast<float4*>(&s->comb[0][row][0])[ch] =
            reinterpret_cast<const float4*>(&g_y1[(b0 + row) * (TT * HH)])[ch];
    }
    __syncthreads();
    cluster_sync_();

    const int prow = tid >> 6, pch = tid & 63;
    int ph0 = 0, ph1 = 0;

    for (int t = 0; t < TT; ++t) {
        const int cur = t & 1, nxt = cur ^ 1;

        float4 yv = make_float4(0.f, 0.f, 0.f, 0.f);
        if (t + 1 < TT)
            yv = *reinterpret_cast<const float4*>(
                &g_y1[(b0 + prow) * (TT * HH) + (t + 1) * HH + pch * 4]);

        const float4* cb0 = reinterpret_cast<const float4*>(s->comb[cur][0]);
        const float4* cb1 = reinterpret_cast<const float4*>(s->comb[cur][1]);
        const float4* cb2 = reinterpret_cast<const float4*>(s->comb[cur][2]);
        const float4* cb3 = reinterpret_cast<const float4*>(s->comb[cur][3]);
        float af0 = 0.f, af1 = 0.f, af2 = 0.f, af3 = 0.f;
        float ac0 = 0.f, ac1 = 0.f, ac2 = 0.f, ac3 = 0.f;

        #pragma unroll
        for (int q = 0; q < 8; ++q) {          // A: y1 region
            const int k4 = q * 8 + ks;
            float4 v;
            v = cb0[k4]; FMA16(af0, ac0, wf[q], wc[q], v)
            v = cb1[k4]; FMA16(af1, ac1, wf[q], wc[q], v)
            v = cb2[k4]; FMA16(af2, ac2, wf[q], wc[q], v)
            v = cb3[k4]; FMA16(af3, ac3, wf[q], wc[q], v)
        }

        if (t) {
            if (t & 1) { mbar_wait_(mb1, ph1); ph1 ^= 1; }
            else       { mbar_wait_(mb0, ph0); ph0 ^= 1; }
            if (tid == 0) mbar_expect_tx_((t & 1) ? mb1 : mb0, P2_TX);
        }

        #pragma unroll
        for (int q = 8; q < 16; ++q) {         // B: h region
            const int k4 = q * 8 + ks;
            float4 v;
            v = cb0[k4]; FMA16(af0, ac0, wf[q], wc[q], v)
            v = cb1[k4]; FMA16(af1, ac1, wf[q], wc[q], v)
            v = cb2[k4]; FMA16(af2, ac2, wf[q], wc[q], v)
            v = cb3[k4]; FMA16(af3, ac3, wf[q], wc[q], v)
        }

        if (t + 1 < TT)
            reinterpret_cast<float4*>(&s->comb[nxt][prow][0])[pch] = yv;

        reinterpret_cast<float4*>(s->partial[tid])[0] = make_float4(af0, af1, af2, af3);
        reinterpret_cast<float4*>(s->partial[tid])[1] = make_float4(ac0, ac1, ac2, ac3);
        __syncthreads();

        // ---- D: alternating writer half; other warps free-run
        const int wtid = tid - ((t & 1) << 7);
        if ((unsigned)wtid < 128u) {
            const int row = wtid >> 5, jl = wtid & 31;
            float pf = s->biasf[jl], pc = s->biasc[jl];
            #pragma unroll
            for (int kk = 0; kk < 8; ++kk) {
                pf += s->partial[kk * 32 + jl][row];
                pc += s->partial[kk * 32 + jl][4 + row];
            }
            float f = sigmoid_(pf);
            float c = tanh_(pc);
            const int jg = j0 + jl;
            float hold = s->comb[cur][row][HH + jg];
            float hn   = fmaf(f, hold - c, c);

            if (t + 1 < TT) {
                uint32_t la = smem_u32(&s->comb[nxt][row][HH + jg]);
                uint32_t lm = ((t + 1) & 1) ? mb1 : mb0;
                #pragma unroll
                for (int p = 0; p < 8; ++p)
                    st_async_f32_(mapa_(la, (uint32_t)p), hn, mapa_(lm, (uint32_t)p));
            }
            out[(b0 + row) * (TT * HH) + t * HH + jg] = hn;              // y2
            if (t == TT - 1)
                out[BB * TT * HH + BB * HH + (b0 + row) * HH + jg] = hn; // hidden L1
        }
    }
    cluster_sync_();   // exit insurance
}

// ================================================================ launch
extern "C" void kernel_launch(void* const* d_in, const int* in_sizes, int n_in,
                              void* d_out, int out_size)
{
    (void)in_sizes; (void)n_in; (void)out_size;
    const float* x   = (const float*)d_in[0];
    const float* Wf1 = (const float*)d_in[1];
    const float* bf1 = (const float*)d_in[2];
    const float* Wc1 = (const float*)d_in[3];
    const float* bc1 = (const float*)d_in[4];
    const float* Wf2 = (const float*)d_in[5];
    const float* bf2 = (const float*)d_in[6];
    const float* Wc2 = (const float*)d_in[7];
    const float* bc2 = (const float*)d_in[8];
    float* out = (float*)d_out;

    cudaFuncSetAttribute(mgu_pass1, cudaFuncAttributeMaxDynamicSharedMemorySize,
                         (int)sizeof(P1Smem));
    cudaFuncSetAttribute(mgu_pass2, cudaFuncAttributeMaxDynamicSharedMemorySize,
                         (int)sizeof(P2Smem));

    mgu_pass1<<<128, 256, sizeof(P1Smem)>>>(x, Wf1, bf1, Wc1, bc1, out);
    mgu_pass2<<<128, 256, sizeof(P2Smem)>>>(Wf2, bf2, Wc2, bc2, out);
}

// round 13
// speedup vs baseline: 1.6777x; 1.1942x over previous
#include <cuda_runtime.h>
#include <cstdint>

#define BB 64
#define TT 1024
#define II 128
#define HH 256

// y1 scratch: [B, T, H] fp32 = 64 MB
__device__ float g_y1[BB * TT * HH];

// ---------------------------------------------------------------- helpers
__device__ __forceinline__ uint32_t smem_u32(const void* p) {
    uint32_t a;
    asm("{ .reg .u64 t; cvta.to.shared.u64 t, %1; cvt.u32.u64 %0, t; }"
        : "=r"(a) : "l"(p));
    return a;
}
__device__ __forceinline__ uint32_t mapa_(uint32_t addr, uint32_t rank) {
    uint32_t ra;
    asm volatile("mapa.shared::cluster.u32 %0, %1, %2;" : "=r"(ra) : "r"(addr), "r"(rank));
    return ra;
}
__device__ __forceinline__ void st_async_f32_(uint32_t dst, float v, uint32_t mbar) {
    asm volatile("st.async.shared::cluster.mbarrier::complete_tx::bytes.b32 [%0], %1, [%2];"
                 :: "r"(dst), "r"(__float_as_uint(v)), "r"(mbar) : "memory");
}
__device__ __forceinline__ void mbar_init_(uint32_t mbar, uint32_t cnt) {
    asm volatile("mbarrier.init.shared.b64 [%0], %1;" :: "r"(mbar), "r"(cnt) : "memory");
}
__device__ __forceinline__ void mbar_expect_tx_(uint32_t mbar, uint32_t bytes) {
    asm volatile("mbarrier.arrive.expect_tx.shared.b64 _, [%0], %1;"
                 :: "r"(mbar), "r"(bytes) : "memory");
}
__device__ __forceinline__ void mbar_wait_(uint32_t mbar, uint32_t parity) {
    asm volatile(
        "{\n\t"
        ".reg .pred P;\n"
        "WL_%=:\n\t"
        "mbarrier.try_wait.parity.acquire.cluster.shared::cta.b64 P, [%0], %1;\n\t"
        "@!P bra WL_%=;\n\t"
        "}" :: "r"(mbar), "r"(parity) : "memory");
}
__device__ __forceinline__ void cluster_sync_() {
    asm volatile("barrier.cluster.arrive.aligned;" ::: "memory");
    asm volatile("barrier.cluster.wait.aligned;" ::: "memory");
}
__device__ __forceinline__ float sigmoid_(float z) {
    return __fdividef(1.0f, 1.0f + __expf(-z));
}
__device__ __forceinline__ float tanh_(float z) {
    return __fdividef(2.0f, 1.0f + __expf(-2.0f * z)) - 1.0f;
}

#define FMA16(af, ac, w0, w1, v)                                  \
    af = fmaf((w0).x, (v).x, af); af = fmaf((w0).y, (v).y, af);   \
    af = fmaf((w0).z, (v).z, af); af = fmaf((w0).w, (v).w, af);   \
    ac = fmaf((w1).x, (v).x, ac); ac = fmaf((w1).y, (v).y, ac);   \
    ac = fmaf((w1).z, (v).z, ac); ac = fmaf((w1).w, (v).w, ac);

// ================================================================ PASS 1
// Layer 1: cluster of 4 CTAs, 2 batch rows per cluster.  (R5 winner, verbatim)
// CTA owns 64 j (BOTH gates), K=384 (x:128|h:256). 256 thr = j(64) x ks(4).
//   q 0..7 reg weights (x, pre-wait) / q 8..15 reg (h) / q 16..23 SMEM (h).
// Phase-D writers: FIXED threads [0,128) every step; warps 4-7 free-run.

#define P1_TX 2048u   // 4 src CTAs x 128 writers x 4B

struct P1Smem {
    float4 w4h[2][32][64];     // weights k4 in [64,96) : 65536 B
    float  comb[2][2][384];    // double-buffered [x_t | h] per row : 6144 B
    float4 partial[256];       // (af0, ac0, af1, ac1) : 4096 B (LDS.128 clean)
    float  biasf[64];
    float  biasc[64];          // 512 B
    unsigned long long mbar[2];
};

__global__ void __cluster_dims__(4, 1, 1) __launch_bounds__(256, 1)
mgu_pass1(const float* __restrict__ x,
          const float* __restrict__ Wf1, const float* __restrict__ bf1,
          const float* __restrict__ Wc1, const float* __restrict__ bc1,
          float* __restrict__ out)
{
    extern __shared__ char raw[];
    P1Smem* s = reinterpret_cast<P1Smem*>(raw);

    const int tid  = threadIdx.x;
    const int rank = blockIdx.x & 3;
    const int cid  = blockIdx.x >> 2;
    const int b0   = cid * 2;
    const int j    = tid & 63;
    const int ks   = tid >> 6;        // 0..3
    const int j0   = rank * 64;
    const int jg_w = j0 + j;

    const uint32_t mb0 = smem_u32(&s->mbar[0]);
    const uint32_t mb1 = smem_u32(&s->mbar[1]);

    // ---- register weights: q = 0..15 (k = 0..255)
    float4 wf[16], wc[16];
    #pragma unroll
    for (int q = 0; q < 16; ++q) {
        const int kb = (q * 4 + ks) * 4;
        wf[q] = make_float4(Wf1[(kb + 0) * HH + jg_w], Wf1[(kb + 1) * HH + jg_w],
                            Wf1[(kb + 2) * HH + jg_w], Wf1[(kb + 3) * HH + jg_w]);
        wc[q] = make_float4(Wc1[(kb + 0) * HH + jg_w], Wc1[(kb + 1) * HH + jg_w],
                            Wc1[(kb + 2) * HH + jg_w], Wc1[(kb + 3) * HH + jg_w]);
    }

    // ---- SMEM weights: k = 256..383 only
    for (int idx = tid; idx < 128 * 64; idx += 256) {
        int kk = idx >> 6, jj = idx & 63;
        int k = 256 + kk;
        reinterpret_cast<float*>(&s->w4h[0][kk >> 2][jj])[kk & 3] = Wf1[k * HH + j0 + jj];
        reinterpret_cast<float*>(&s->w4h[1][kk >> 2][jj])[kk & 3] = Wc1[k * HH + j0 + jj];
    }
    if (tid < 64) { s->biasf[tid] = bf1[j0 + tid]; s->biasc[tid] = bc1[j0 + tid]; }

    if (tid == 0) {
        mbar_init_(mb0, 1);  mbar_init_(mb1, 1);
        mbar_expect_tx_(mb0, P1_TX);  mbar_expect_tx_(mb1, P1_TX);
    }

    // ---- comb init: zero both buffers, then x(0)
    for (int idx = tid; idx < 2 * 2 * 384; idx += 256)
        reinterpret_cast<float*>(s->comb)[idx] = 0.0f;
    __syncthreads();
    if (tid < 64) {
        int row = tid >> 5, ch = tid & 31;
        reinterpret_cast<float4*>(&s->comb[0][row][0])[ch] =
            reinterpret_cast<const float4*>(&x[(b0 + row) * (TT * II)])[ch];
    }
    __syncthreads();
    cluster_sync_();   // peers' mbarriers + buffers ready before any st.async

    const int prow = tid >> 5, pch = tid & 31;   // x staging map (tid < 64)
    int ph0 = 0, ph1 = 0;

    for (int t = 0; t < TT; ++t) {
        const int cur = t & 1, nxt = cur ^ 1;

        float4 xv = make_float4(0.f, 0.f, 0.f, 0.f);
        if (tid < 64 && t + 1 < TT)
            xv = *reinterpret_cast<const float4*>(
                &x[(b0 + prow) * (TT * II) + (t + 1) * II + pch * 4]);

        const float4* cb0 = reinterpret_cast<const float4*>(s->comb[cur][0]);
        const float4* cb1 = reinterpret_cast<const float4*>(s->comb[cur][1]);
        float af0 = 0.f, ac0 = 0.f, af1 = 0.f, ac1 = 0.f;

        // ---- A: x-portion, register weights (hides mbar wait)
        #pragma unroll
        for (int q = 0; q < 8; ++q) {
            const int k4 = q * 4 + ks;
            float4 v0 = cb0[k4];
            float4 v1 = cb1[k4];
            FMA16(af0, ac0, wf[q], wc[q], v0)
            FMA16(af1, ac1, wf[q], wc[q], v1)
        }

        if (t) {
            if (t & 1) { mbar_wait_(mb1, ph1); ph1 ^= 1; }
            else       { mbar_wait_(mb0, ph0); ph0 ^= 1; }
            if (tid == 0) mbar_expect_tx_((t & 1) ? mb1 : mb0, P1_TX);  // re-arm t+2
        }

        // ---- B1: h-portion, register weights
        #pragma unroll
        for (int q = 8; q < 16; ++q) {
            const int k4 = q * 4 + ks;
            float4 v0 = cb0[k4];
            float4 v1 = cb1[k4];
            FMA16(af0, ac0, wf[q], wc[q], v0)
            FMA16(af1, ac1, wf[q], wc[q], v1)
        }
        // ---- B2: h-portion tail, SMEM weights (k4 64..95)
        #pragma unroll
        for (int q = 0; q < 8; ++q) {
            const int k4 = 64 + q * 4 + ks;
            float4 w0 = s->w4h[0][k4 - 64][j];
            float4 w1 = s->w4h[1][k4 - 64][j];
            float4 v0 = cb0[k4];
            float4 v1 = cb1[k4];
            FMA16(af0, ac0, w0, w1, v0)
            FMA16(af1, ac1, w0, w1, v1)
        }

        // stage x(t+1)
        if (tid < 64 && t + 1 < TT)
            reinterpret_cast<float4*>(&s->comb[nxt][prow][0])[pch] = xv;

        s->partial[tid] = make_float4(af0, ac0, af1, ac1);
        __syncthreads();

        // ---- D: fixed writers 0..127; warps 4-7 free-run into next dot-A
        if (tid < 128) {
            const int row = tid >> 6, jl = tid & 63;
            float4 p0 = s->partial[jl];
            float4 p1 = s->partial[64 + jl];
            float4 p2 = s->partial[128 + jl];
            float4 p3 = s->partial[192 + jl];
            float pf, pc;
            if (row == 0) { pf = (p0.x + p1.x) + (p2.x + p3.x);
                            pc = (p0.y + p1.y) + (p2.y + p3.y); }
            else          { pf = (p0.z + p1.z) + (p2.z + p3.z);
                            pc = (p0.w + p1.w) + (p2.w + p3.w); }
            pf += s->biasf[jl];
            pc += s->biasc[jl];
            float f = sigmoid_(pf);
            float c = tanh_(pc);
            const int jg = j0 + jl;
            float hold = s->comb[cur][row][II + jg];
            float hn   = fmaf(f, hold - c, c);     // f*h + (1-f)*c

            if (t + 1 < TT) {
                uint32_t la = smem_u32(&s->comb[nxt][row][II + jg]);
                uint32_t lm = ((t + 1) & 1) ? mb1 : mb0;
                #pragma unroll
                for (int p = 0; p < 4; ++p)
                    st_async_f32_(mapa_(la, (uint32_t)p), hn, mapa_(lm, (uint32_t)p));
            }
            g_y1[(b0 + row) * (TT * HH) + t * HH + jg] = hn;
            if (t == TT - 1)
                out[BB * TT * HH + (b0 + row) * HH + jg] = hn;   // hidden layer 0
        }
    }
    cluster_sync_();   // exit insurance
}

// ================================================================ PASS 2
// Layer 2: cluster of 8 CTAs, 4 batch rows per cluster.  (R5 + conflict-free
// partial planes)
// CTA owns 32 j (BOTH gates), K=512 (y1:256|h:256). 256 thr = j(32) x ks(8).
// ALL weights register-resident. Fixed writers [0,128).
// partial planes part[c][256]: c = 0..3 -> af(row c), 4..7 -> ac(row c).
//   store: part[c][tid]           bank = lane  -> conflict-free
//   read : part[row][kk*32 + jl]  bank = jl    -> conflict-free
// (was float[256][8]: reads were 8-way bank-conflicted)

#define P2_TX 4096u   // 8 src CTAs x 128 writers x 4B

struct P2Smem {
    float  comb[2][4][512];    // 16384 B
    float  part[8][256];       // scalar planes : 8192 B
    float  biasf[32];
    float  biasc[32];          // 256 B
    unsigned long long mbar[2];
};

__global__ void __cluster_dims__(8, 1, 1) __launch_bounds__(256, 1)
mgu_pass2(const float* __restrict__ Wf2, const float* __restrict__ bf2,
          const float* __restrict__ Wc2, const float* __restrict__ bc2,
          float* __restrict__ out)
{
    extern __shared__ char raw[];
    P2Smem* s = reinterpret_cast<P2Smem*>(raw);

    const int tid  = threadIdx.x;
    const int rank = blockIdx.x & 7;
    const int cid  = blockIdx.x >> 3;
    const int b0   = cid * 4;
    const int j    = tid & 31;
    const int ks   = tid >> 5;        // 0..7
    const int j0   = rank * 32;
    const int jg_w = j0 + j;

    const uint32_t mb0 = smem_u32(&s->mbar[0]);
    const uint32_t mb1 = smem_u32(&s->mbar[1]);

    // ---- ALL weights into registers: q = 0..15, k4 = q*8+ks
    float4 wf[16], wc[16];
    #pragma unroll
    for (int q = 0; q < 16; ++q) {
        const int kb = (q * 8 + ks) * 4;
        wf[q] = make_float4(Wf2[(kb + 0) * HH + jg_w], Wf2[(kb + 1) * HH + jg_w],
                            Wf2[(kb + 2) * HH + jg_w], Wf2[(kb + 3) * HH + jg_w]);
        wc[q] = make_float4(Wc2[(kb + 0) * HH + jg_w], Wc2[(kb + 1) * HH + jg_w],
                            Wc2[(kb + 2) * HH + jg_w], Wc2[(kb + 3) * HH + jg_w]);
    }
    if (tid < 32) { s->biasf[tid] = bf2[j0 + tid]; s->biasc[tid] = bc2[j0 + tid]; }

    if (tid == 0) {
        mbar_init_(mb0, 1);  mbar_init_(mb1, 1);
        mbar_expect_tx_(mb0, P2_TX);  mbar_expect_tx_(mb1, P2_TX);
    }

    for (int idx = tid; idx < 2 * 4 * 512; idx += 256)
        reinterpret_cast<float*>(s->comb)[idx] = 0.0f;
    __syncthreads();
    {
        int row = tid >> 6, ch = tid & 63;    // 4 rows x 64 float4
        reinterpret_cast<float4*>(&s->comb[0][row][0])[ch] =
            reinterpret_cast<const float4*>(&g_y1[(b0 + row) * (TT * HH)])[ch];
    }
    __syncthreads();
    cluster_sync_();

    const int prow = tid >> 6, pch = tid & 63;
    int ph0 = 0, ph1 = 0;

    for (int t = 0; t < TT; ++t) {
        const int cur = t & 1, nxt = cur ^ 1;

        float4 yv = make_float4(0.f, 0.f, 0.f, 0.f);
        if (t + 1 < TT)
            yv = *reinterpret_cast<const float4*>(
                &g_y1[(b0 + prow) * (TT * HH) + (t + 1) * HH + pch * 4]);

        const float4* cb0 = reinterpret_cast<const float4*>(s->comb[cur][0]);
        const float4* cb1 = reinterpret_cast<const float4*>(s->comb[cur][1]);
        const float4* cb2 = reinterpret_cast<const float4*>(s->comb[cur][2]);
        const float4* cb3 = reinterpret_cast<const float4*>(s->comb[cur][3]);
        float af0 = 0.f, af1 = 0.f, af2 = 0.f, af3 = 0.f;
        float ac0 = 0.f, ac1 = 0.f, ac2 = 0.f, ac3 = 0.f;

        #pragma unroll
        for (int q = 0; q < 8; ++q) {          // A: y1 region
            const int k4 = q * 8 + ks;
            float4 v;
            v = cb0[k4]; FMA16(af0, ac0, wf[q], wc[q], v)
            v = cb1[k4]; FMA16(af1, ac1, wf[q], wc[q], v)
            v = cb2[k4]; FMA16(af2, ac2, wf[q], wc[q], v)
            v = cb3[k4]; FMA16(af3, ac3, wf[q], wc[q], v)
        }

        if (t) {
            if (t & 1) { mbar_wait_(mb1, ph1); ph1 ^= 1; }
            else       { mbar_wait_(mb0, ph0); ph0 ^= 1; }
            if (tid == 0) mbar_expect_tx_((t & 1) ? mb1 : mb0, P2_TX);
        }

        #pragma unroll
        for (int q = 8; q < 16; ++q) {         // B: h region
            const int k4 = q * 8 + ks;
            float4 v;
            v = cb0[k4]; FMA16(af0, ac0, wf[q], wc[q], v)
            v = cb1[k4]; FMA16(af1, ac1, wf[q], wc[q], v)
            v = cb2[k4]; FMA16(af2, ac2, wf[q], wc[q], v)
            v = cb3[k4]; FMA16(af3, ac3, wf[q], wc[q], v)
        }

        if (t + 1 < TT)
            reinterpret_cast<float4*>(&s->comb[nxt][prow][0])[pch] = yv;

        // ---- partial planes (conflict-free scalar stores)
        s->part[0][tid] = af0;  s->part[1][tid] = af1;
        s->part[2][tid] = af2;  s->part[3][tid] = af3;
        s->part[4][tid] = ac0;  s->part[5][tid] = ac1;
        s->part[6][tid] = ac2;  s->part[7][tid] = ac3;
        __syncthreads();

        // ---- D: fixed writers 0..127; warps 4-7 free-run
        if (tid < 128) {
            const int row = tid >> 5, jl = tid & 31;
            const float* pfp = s->part[row];
            const float* pcp = s->part[4 + row];
            float pf = s->biasf[jl], pc = s->biasc[jl];
            #pragma unroll
            for (int kk = 0; kk < 8; ++kk) {
                pf += pfp[kk * 32 + jl];
                pc += pcp[kk * 32 + jl];
            }
            float f = sigmoid_(pf);
            float c = tanh_(pc);
            const int jg = j0 + jl;
            float hold = s->comb[cur][row][HH + jg];
            float hn   = fmaf(f, hold - c, c);

            if (t + 1 < TT) {
                uint32_t la = smem_u32(&s->comb[nxt][row][HH + jg]);
                uint32_t lm = ((t + 1) & 1) ? mb1 : mb0;
                #pragma unroll
                for (int p = 0; p < 8; ++p)
                    st_async_f32_(mapa_(la, (uint32_t)p), hn, mapa_(lm, (uint32_t)p));
            }
            out[(b0 + row) * (TT * HH) + t * HH + jg] = hn;              // y2
            if (t == TT - 1)
                out[BB * TT * HH + BB * HH + (b0 + row) * HH + jg] = hn; // hidden L1
        }
    }
    cluster_sync_();   // exit insurance
}

// ================================================================ launch
extern "C" void kernel_launch(void* const* d_in, const int* in_sizes, int n_in,
                              void* d_out, int out_size)
{
    (void)in_sizes; (void)n_in; (void)out_size;
    const float* x   = (const float*)d_in[0];
    const float* Wf1 = (const float*)d_in[1];
    const float* bf1 = (const float*)d_in[2];
    const float* Wc1 = (const float*)d_in[3];
    const float* bc1 = (const float*)d_in[4];
    const float* Wf2 = (const float*)d_in[5];
    const float* bf2 = (const float*)d_in[6];
    const float* Wc2 = (const float*)d_in[7];
    const float* bc2 = (const float*)d_in[8];
    float* out = (float*)d_out;

    cudaFuncSetAttribute(mgu_pass1, cudaFuncAttributeMaxDynamicSharedMemorySize,
                         (int)sizeof(P1Smem));
    cudaFuncSetAttribute(mgu_pass2, cudaFuncAttributeMaxDynamicSharedMemorySize,
                         (int)sizeof(P2Smem));

    mgu_pass1<<<128, 256, sizeof(P1Smem)>>>(x, Wf1, bf1, Wc1, bc1, out);
    mgu_pass2<<<128, 256, sizeof(P2Smem)>>>(Wf2, bf2, Wc2, bc2, out);
}